// round 13
// baseline (speedup 1.0000x reference)
#include <cuda_runtime.h>
#include <cstdint>

#define LOG2E 1.4426950408889634f

// ---------------- scratch ----------------
__device__ float g_Wh[8 * 1024 * 256];     // [b][n][h*32+d]
__device__ float g_e1[8 * 8 * 1024];
__device__ float g_e2[8 * 8 * 1024];
__device__ float g_maxe2[64];

// ---------------- f32x2 helpers ----------------
__device__ __forceinline__ void fma2(unsigned long long& d, unsigned long long a,
                                     unsigned long long b) {
    asm("fma.rn.f32x2 %0, %1, %2, %0;" : "+l"(d) : "l"(a), "l"(b));
}
__device__ __forceinline__ unsigned long long add2(unsigned long long a,
                                                   unsigned long long b) {
    unsigned long long r;
    asm("add.rn.f32x2 %0, %1, %2;" : "=l"(r) : "l"(a), "l"(b));
    return r;
}
__device__ __forceinline__ unsigned long long dup2(float v) {
    unsigned long long r;
    asm("mov.b64 %0, {%1,%1};" : "=l"(r) : "f"(v));
    return r;
}
__device__ __forceinline__ void upk2(unsigned long long v, float& lo, float& hi) {
    asm("mov.b64 {%0,%1}, %2;" : "=f"(lo), "=f"(hi) : "l"(v));
}
__device__ __forceinline__ float ex2(float x) {
    float r;
    asm("ex2.approx.ftz.f32 %0, %1;" : "=f"(r) : "f"(x));
    return r;
}

// ---------------- kernel 1: Wh = nf(8192x256) @ Wcat(256x256) ----------------
// 128x64 tile, grid 64x4 = 256 CTAs -> ~2 CTAs/SM for latency hiding.
__global__ void __launch_bounds__(256)
gemm_wh_kernel(const float* __restrict__ A, const float* __restrict__ Wm) {
    __shared__ __align__(16) float as[16][132];
    __shared__ __align__(16) float bs[16][64];

    const int row0 = blockIdx.x * 128;
    const int col0 = blockIdx.y * 64;
    const int t = threadIdx.x;
    const int tx = t & 15, ty = t >> 4;

    unsigned long long acc[8][2];
#pragma unroll
    for (int r = 0; r < 8; r++) { acc[r][0] = 0ull; acc[r][1] = 0ull; }

    float4 a_reg[2], b_reg;

    auto load_tile = [&](int k0) {
#pragma unroll
        for (int l = 0; l < 2; l++) {
            int e = t + l * 256;
            int r = e >> 2, kq = e & 3;
            a_reg[l] = *(const float4*)&A[(size_t)(row0 + r) * 256 + k0 + kq * 4];
        }
        {
            int kk = t >> 4, cq = t & 15;
            int c = col0 + cq * 4;
            b_reg = *(const float4*)&Wm[(size_t)(c >> 5) * 8192 +
                                        (size_t)(k0 + kk) * 32 + (c & 31)];
        }
    };

    load_tile(0);

    for (int k0 = 0; k0 < 256; k0 += 16) {
#pragma unroll
        for (int l = 0; l < 2; l++) {
            int e = t + l * 256;
            int r = e >> 2, kq = e & 3;
            as[kq * 4 + 0][r] = a_reg[l].x;
            as[kq * 4 + 1][r] = a_reg[l].y;
            as[kq * 4 + 2][r] = a_reg[l].z;
            as[kq * 4 + 3][r] = a_reg[l].w;
        }
        {
            int kk = t >> 4, cq = t & 15;
            *(float4*)&bs[kk][cq * 4] = b_reg;
        }
        __syncthreads();

        if (k0 + 16 < 256) load_tile(k0 + 16);

#pragma unroll
        for (int kk = 0; kk < 16; kk++) {
            float4 a0 = *(const float4*)&as[kk][ty * 4];
            float4 a1 = *(const float4*)&as[kk][ty * 4 + 64];
            ulonglong2 b0 = *(const ulonglong2*)&bs[kk][tx * 4];
            unsigned long long ad[8];
            ad[0] = dup2(a0.x); ad[1] = dup2(a0.y); ad[2] = dup2(a0.z); ad[3] = dup2(a0.w);
            ad[4] = dup2(a1.x); ad[5] = dup2(a1.y); ad[6] = dup2(a1.z); ad[7] = dup2(a1.w);
#pragma unroll
            for (int r = 0; r < 8; r++) {
                fma2(acc[r][0], b0.x, ad[r]);
                fma2(acc[r][1], b0.y, ad[r]);
            }
        }
        __syncthreads();
    }

#pragma unroll
    for (int r = 0; r < 8; r++) {
        int gr = row0 + ((r < 4) ? (ty * 4 + r) : (64 + ty * 4 + r - 4));
        float4 o;
        upk2(acc[r][0], o.x, o.y);
        upk2(acc[r][1], o.z, o.w);
        *(float4*)&g_Wh[(size_t)gr * 256 + col0 + tx * 4] = o;
    }
}

// ---------------- kernel 2: e1, e2, max(e2) per (b,h) ----------------
__global__ void compute_e_kernel(const float* __restrict__ a) {
    const int bh = blockIdx.x;
    const int b = bh >> 3, h = bh & 7;
    const int tid = threadIdx.x;
    const int warp = tid >> 5, lane = tid & 31;

    const float a1v = a[h * 64 + lane];
    const float a2v = a[h * 64 + 32 + lane];
    __shared__ float wmax[8];

    const float* base = g_Wh + (size_t)(b * 1024) * 256 + h * 32;
    float mx = -1e30f;

    for (int nn = 0; nn < 128; nn++) {
        int n = warp * 128 + nn;
        float wh = base[(size_t)n * 256 + lane];
        float x = wh * a1v;
        float y = wh * a2v;
#pragma unroll
        for (int s = 16; s >= 1; s >>= 1) {
            x += __shfl_xor_sync(0xffffffffu, x, s);
            y += __shfl_xor_sync(0xffffffffu, y, s);
        }
        if (lane == 0) {
            g_e1[bh * 1024 + n] = x;
            g_e2[bh * 1024 + n] = y;
        }
        mx = fmaxf(mx, y);
    }
    if (lane == 0) wmax[warp] = mx;
    __syncthreads();
    if (tid == 0) {
        float m = wmax[0];
#pragma unroll
        for (int w = 1; w < 8; w++) m = fmaxf(m, wmax[w]);
        g_maxe2[bh] = m;
    }
}

// ---------------- kernel 3: fused masked softmax + P @ Wh + bias + relu ----------------
// R=8 rows/warp. Row-pair f32x2 accumulators: p comes as natural pairs from smem,
// Wh duplicated via registers. Cross-tile adjacency prefetch hides LDG latency.
#define PW_WARP 1056
#define ATTN_SMEM ((32768 + 1024 + 16 * PW_WARP) * 4)

__global__ void __launch_bounds__(512, 1)
gat_attn_kernel(const int* __restrict__ adj, const float* __restrict__ bias,
                float* __restrict__ out) {
    extern __shared__ __align__(16) float smem[];
    float* whs = smem;                    // 32768 floats
    float* e2s = smem + 32768;            // 1024 floats
    float* pbase = smem + 32768 + 1024;   // 16 * 1056 floats

    const int bh = blockIdx.x >> 1;
    const int hv = blockIdx.x & 1;
    const int b = bh >> 3, h = bh & 7;
    const int tid = threadIdx.x;

    // stage Wh slice of this (b,h): all 1024 j, 32 dims
    const float4* gbase = (const float4*)(g_Wh) + ((size_t)b * 1024 * 256 + h * 32) / 4;
    float4* whs4 = (float4*)whs;
    for (int f = tid; f < 8192; f += 512) {
        int j = f >> 3, q = f & 7;
        whs4[f] = gbase[(size_t)j * 64 + q];
    }
    for (int n = tid; n < 1024; n += 512) e2s[n] = g_e2[bh * 1024 + n];
    __syncthreads();

    const float maxe2 = g_maxe2[bh];
    const int warp = tid >> 5, lane = tid & 31;
    const int dg = lane & 7, jjq = lane >> 3;
    float* pw = pbase + warp * PW_WARP;           // bufA: [0,528), bufB: [528,1056)
    const float* e1p = g_e1 + bh * 1024;
    const float4 bias4 = ((const float4*)(bias + h * 32))[dg];
    const int jb = lane << 2;

    // reader base offsets (16B units): jjq*33 within each buffer
    const float* prA = pw + jjq * 33 * 4;
    const float* prB = pw + 528 + jjq * 33 * 4;

    for (int grp = 0; grp < 4; grp++) {
        const int i0 = hv * 512 + ((grp * 16 + warp) << 3);   // 8-row group
        const int* adjrow = adj + (size_t)(b * 1024 + i0) * 1024;

        float e1v[8], mneg[8];
        float4 e14a = *(const float4*)&e1p[i0];
        float4 e14b = *(const float4*)&e1p[i0 + 4];
        e1v[0] = e14a.x; e1v[1] = e14a.y; e1v[2] = e14a.z; e1v[3] = e14a.w;
        e1v[4] = e14b.x; e1v[5] = e14b.y; e1v[6] = e14b.z; e1v[7] = e14b.w;
#pragma unroll
        for (int r = 0; r < 8; r++) {
            float s = e1v[r] + maxe2;
            s = fmaxf(s, 0.2f * s);           // leaky upper bound on all scores of row i
            mneg[r] = -s * LOG2E;
        }

        // prefetch adjacency for first tile (8 x LDG.128, batched)
        int4 abuf[8];
#pragma unroll
        for (int r = 0; r < 8; r++) abuf[r] = *(const int4*)&adjrow[r * 1024 + jb];

        // acc[p][d] = f32x2 pair (out[2p][d], out[2p+1][d]), d = dg*4+d
        unsigned long long acc[4][4];
#pragma unroll
        for (int p = 0; p < 4; p++)
#pragma unroll
            for (int d = 0; d < 4; d++) acc[p][d] = 0ull;
        float sums[8] = {0.f, 0.f, 0.f, 0.f, 0.f, 0.f, 0.f, 0.f};

        for (int c0 = 0; c0 < 1024; c0 += 128) {
            // ---- phase A: scores+exp, lane owns 4 consecutive j ----
            float4 ej4 = *(const float4*)&e2s[c0 + jb];
            float ej[4] = {ej4.x, ej4.y, ej4.z, ej4.w};
            {
                float pv[4][4];
#pragma unroll
                for (int r = 0; r < 4; r++) {
                    int am[4] = {abuf[r].x, abuf[r].y, abuf[r].z, abuf[r].w};
#pragma unroll
                    for (int m = 0; m < 4; m++) {
                        float s = e1v[r] + ej[m];
                        s = fmaxf(s, 0.2f * s);
                        float arg = am[m] ? fmaf(s, LOG2E, mneg[r]) : -10000.0f;
                        pv[r][m] = ex2(arg);
                    }
                    sums[r] += (pv[r][0] + pv[r][1]) + (pv[r][2] + pv[r][3]);
                }
#pragma unroll
                for (int m = 0; m < 4; m++)
                    *(float4*)&pw[(m * 33 + lane) * 4] =
                        make_float4(pv[0][m], pv[1][m], pv[2][m], pv[3][m]);
            }
            {
                float pv[4][4];
#pragma unroll
                for (int r = 0; r < 4; r++) {
                    int am[4] = {abuf[r + 4].x, abuf[r + 4].y, abuf[r + 4].z, abuf[r + 4].w};
#pragma unroll
                    for (int m = 0; m < 4; m++) {
                        float s = e1v[r + 4] + ej[m];
                        s = fmaxf(s, 0.2f * s);
                        float arg = am[m] ? fmaf(s, LOG2E, mneg[r + 4]) : -10000.0f;
                        pv[r][m] = ex2(arg);
                    }
                    sums[r + 4] += (pv[r][0] + pv[r][1]) + (pv[r][2] + pv[r][3]);
                }
#pragma unroll
                for (int m = 0; m < 4; m++)
                    *(float4*)&pw[528 + (m * 33 + lane) * 4] =
                        make_float4(pv[0][m], pv[1][m], pv[2][m], pv[3][m]);
            }

            // prefetch adjacency for next tile (hidden under phase B)
            if (c0 + 128 < 1024) {
#pragma unroll
                for (int r = 0; r < 8; r++)
                    abuf[r] = *(const int4*)&adjrow[r * 1024 + c0 + 128 + jb];
            }
            __syncwarp();

            // ---- phase B: acc += P * Wh. reader j = c0 + blk*4 + jjq ----
            const ulonglong2* wrow =
                (const ulonglong2*)(whs4 + (size_t)(c0 + jjq) * 8 + dg);
#pragma unroll 4
            for (int blk = 0; blk < 32; blk++) {
                ulonglong2 wv = wrow[blk * 32];               // w[dg*4 .. +3]
                ulonglong2 pa = *(const ulonglong2*)(prA + blk * 4);  // (p0,p1),(p2,p3)
                ulonglong2 pb = *(const ulonglong2*)(prB + blk * 4);  // (p4,p5),(p6,p7)
                float w0, w1, w2, w3;
                upk2(wv.x, w0, w1);
                upk2(wv.y, w2, w3);
                unsigned long long d0 = dup2(w0), d1 = dup2(w1),
                                   d2 = dup2(w2), d3 = dup2(w3);
                fma2(acc[0][0], d0, pa.x); fma2(acc[0][1], d1, pa.x);
                fma2(acc[0][2], d2, pa.x); fma2(acc[0][3], d3, pa.x);
                fma2(acc[1][0], d0, pa.y); fma2(acc[1][1], d1, pa.y);
                fma2(acc[1][2], d2, pa.y); fma2(acc[1][3], d3, pa.y);
                fma2(acc[2][0], d0, pb.x); fma2(acc[2][1], d1, pb.x);
                fma2(acc[2][2], d2, pb.x); fma2(acc[2][3], d3, pb.x);
                fma2(acc[3][0], d0, pb.y); fma2(acc[3][1], d1, pb.y);
                fma2(acc[3][2], d2, pb.y); fma2(acc[3][3], d3, pb.y);
            }
            __syncwarp();
        }

        // reduce partial accs over the 4 jj-quarters (lanes xor 8, 16)
#pragma unroll
        for (int p = 0; p < 4; p++)
#pragma unroll
            for (int d = 0; d < 4; d++) {
                acc[p][d] = add2(acc[p][d], __shfl_xor_sync(0xffffffffu, acc[p][d], 8));
                acc[p][d] = add2(acc[p][d], __shfl_xor_sync(0xffffffffu, acc[p][d], 16));
            }
#pragma unroll
        for (int r = 0; r < 8; r++) {
            float s = sums[r];
#pragma unroll
            for (int m = 16; m >= 1; m >>= 1) s += __shfl_xor_sync(0xffffffffu, s, m);
            sums[r] = s;
        }

        // epilogue: normalize, +bias, relu, store (lanes 0..7 store)
#pragma unroll
        for (int p = 0; p < 4; p++) {
            float lo[4], hi[4];
#pragma unroll
            for (int d = 0; d < 4; d++) upk2(acc[p][d], lo[d], hi[d]);
            float inv0 = 1.0f / sums[2 * p];
            float inv1 = 1.0f / sums[2 * p + 1];
            float4 o0, o1;
            o0.x = fmaxf(fmaf(lo[0], inv0, bias4.x), 0.0f);
            o0.y = fmaxf(fmaf(lo[1], inv0, bias4.y), 0.0f);
            o0.z = fmaxf(fmaf(lo[2], inv0, bias4.z), 0.0f);
            o0.w = fmaxf(fmaf(lo[3], inv0, bias4.w), 0.0f);
            o1.x = fmaxf(fmaf(hi[0], inv1, bias4.x), 0.0f);
            o1.y = fmaxf(fmaf(hi[1], inv1, bias4.y), 0.0f);
            o1.z = fmaxf(fmaf(hi[2], inv1, bias4.z), 0.0f);
            o1.w = fmaxf(fmaf(hi[3], inv1, bias4.w), 0.0f);
            if (jjq == 0) {
                float* ob = out + (size_t)((b << 10) + i0 + 2 * p) * 256 + (h << 5) + (dg << 2);
                *(float4*)ob = o0;
                *(float4*)(ob + 256) = o1;
            }
        }
    }
}

// ---------------- launch ----------------
extern "C" void kernel_launch(void* const* d_in, const int* in_sizes, int n_in,
                              void* d_out, int out_size) {
    const float* nf   = (const float*)d_in[0];
    const int*   adj  = (const int*)d_in[1];
    const float* Wm   = (const float*)d_in[2];
    const float* av   = (const float*)d_in[3];
    const float* bias = (const float*)d_in[4];
    float* out = (float*)d_out;

    gemm_wh_kernel<<<dim3(64, 4, 1), 256>>>(nf, Wm);
    compute_e_kernel<<<64, 256>>>(av);
    cudaFuncSetAttribute(gat_attn_kernel,
                         cudaFuncAttributeMaxDynamicSharedMemorySize, ATTN_SMEM);
    gat_attn_kernel<<<128, 512, ATTN_SMEM>>>(adj, bias, out);
}